// round 3
// baseline (speedup 1.0000x reference)
#include <cuda_runtime.h>

#define NN 524288
#define EE 8388608
#define NPG 8192
#define NB 64
#define NWORDS (NN/32)
#define CAP0 (1<<20)
#define CAP1 (1<<22)

__device__ __align__(128) float g_deg[NN];
__device__ __align__(128) float g_dis[NN];
__device__ __align__(128) float g_h[NN*8];      // h1, later h2
__device__ __align__(128) float g_agg1[NN*8];
__device__ __align__(128) float g_agg2[NN*8];
__device__ __align__(128) float g_h3v[NN];
__device__ __align__(128) float g_agg3[NN];
__device__ unsigned g_bm0[NWORDS];   // targets
__device__ unsigned g_bm1[NWORDS];   // S1 = targets U src(list0)
__device__ unsigned g_bm2[NWORDS];   // src(list1)
__device__ int g_list0[CAP0];
__device__ int g_list1[CAP1];
__device__ int g_nl1[NN];
__device__ int g_nl2[NN];
__device__ int g_cnt0, g_cnt1, g_cntn1, g_cntn2;

__device__ __forceinline__ bool bmtest(const unsigned* bm, int i){ return (bm[i>>5]>>(i&31))&1u; }
__device__ __forceinline__ void bmset(unsigned* bm, int i){ atomicOr(&bm[i>>5], 1u<<(i&31)); }

__device__ __forceinline__ void wappend(bool pred, int val, int* cnt, int* list, int cap){
  unsigned m = __ballot_sync(0xffffffffu, pred);
  if (!m) return;
  int lane = threadIdx.x & 31;
  int leader = __ffs(m) - 1;
  int base = 0;
  if (lane == leader) base = atomicAdd(cnt, __popc(m));
  base = __shfl_sync(0xffffffffu, base, leader);
  if (pred){
    int p = base + __popc(m & ((1u<<lane)-1u));
    if (p < cap) list[p] = val;
  }
}

__global__ void k_init(){
  int i = blockIdx.x*blockDim.x + threadIdx.x;
  g_deg[i] = 1.0f;
  if (i < NWORDS){ g_bm0[i]=0u; g_bm1[i]=0u; g_bm2[i]=0u; }
  if (i == 0){ g_cnt0=0; g_cnt1=0; g_cntn1=0; g_cntn2=0; }
}

__global__ void k_mark(const int* __restrict__ tgt){
  int g = threadIdx.x;
  int t = g*NPG + tgt[g];
  bmset(g_bm0, t); bmset(g_bm1, t);
}

__global__ __launch_bounds__(256) void k_deg(const int* __restrict__ dstp){
  int e = blockIdx.x*blockDim.x + threadIdx.x;
  int d = dstp[e];
  atomicAdd(&g_deg[d], 1.0f);
  wappend(bmtest(g_bm0, d), e, &g_cnt0, g_list0, CAP0);
}

__global__ void k_srcs(const int* __restrict__ srcp, int which){
  const int* list = which ? g_list1 : g_list0;
  int cap = which ? CAP1 : CAP0;
  int n = min(which ? g_cnt1 : g_cnt0, cap);
  unsigned* bm = which ? g_bm2 : g_bm1;
  int stride = gridDim.x*blockDim.x;
  for (int i = blockIdx.x*blockDim.x + threadIdx.x; i < n; i += stride)
    bmset(bm, srcp[list[i]]);
}

__global__ void k_dis(){
  int i = blockIdx.x*blockDim.x + threadIdx.x;
  g_dis[i] = rsqrtf(g_deg[i]);
}

// h1 = x@W1; agg1 init = h1/deg + b1.  8 threads/node.
__global__ __launch_bounds__(256) void k_h1(const float* __restrict__ x,
                                            const float* __restrict__ W1,
                                            const float* __restrict__ b1){
  __shared__ float sW[128*9];
  __shared__ float sb[8];
  int tid = threadIdx.x;
  for (int i = tid; i < 1024; i += 256) sW[(i>>3)*9 + (i&7)] = W1[i];
  if (tid < 8) sb[tid] = b1[tid];
  __syncthreads();
  int sub  = tid & 7;
  int node = blockIdx.x*32 + (tid>>3);
  const float* xr = x + (size_t)node*128 + sub*4;
  float acc[8];
  #pragma unroll
  for (int j=0;j<8;j++) acc[j] = 0.f;
  #pragma unroll
  for (int q=0;q<4;q++){
    float4 v = *(const float4*)(xr + 32*q);
    float xt[4] = {v.x, v.y, v.z, v.w};
    #pragma unroll
    for (int t=0;t<4;t++){
      const float* w = &sW[(32*q + 4*sub + t)*9];
      #pragma unroll
      for (int j=0;j<8;j++) acc[j] += xt[t]*w[j];
    }
  }
  #pragma unroll
  for (int off=4; off; off>>=1){
    #pragma unroll
    for (int j=0;j<8;j++) acc[j] += __shfl_xor_sync(0xffffffffu, acc[j], off);
  }
  if (sub == 0){
    float r = g_dis[node];
    float inv = r*r;
    float* hp = g_h + (size_t)node*8;
    *(float4*)hp     = make_float4(acc[0],acc[1],acc[2],acc[3]);
    *(float4*)(hp+4) = make_float4(acc[4],acc[5],acc[6],acc[7]);
    float* ap = g_agg1 + (size_t)node*8;
    *(float4*)ap     = make_float4(acc[0]*inv+sb[0],acc[1]*inv+sb[1],acc[2]*inv+sb[2],acc[3]*inv+sb[3]);
    *(float4*)(ap+4) = make_float4(acc[4]*inv+sb[4],acc[5]*inv+sb[5],acc[6]*inv+sb[6],acc[7]*inv+sb[7]);
  }
}

__global__ __launch_bounds__(256) void k_agg1(const int* __restrict__ srcp, const int* __restrict__ dstp){
  int e = blockIdx.x*blockDim.x + threadIdx.x;
  int s = srcp[e], d = dstp[e];
  float c = g_dis[s]*g_dis[d];
  const float* hp = g_h + (size_t)s*8;
  float4 a = *(const float4*)hp, b = *(const float4*)(hp+4);
  a.x*=c; a.y*=c; a.z*=c; a.w*=c;
  b.x*=c; b.y*=c; b.z*=c; b.w*=c;
  float* ap = g_agg1 + (size_t)d*8;
  atomicAdd((float4*)ap, a);
  atomicAdd((float4*)(ap+4), b);
  wappend(bmtest(g_bm1, d), e, &g_cnt1, g_list1, CAP1);
}

__global__ void k_compact(){
  int i = blockIdx.x*blockDim.x + threadIdx.x;
  bool p1 = bmtest(g_bm1, i);
  bool p2 = p1 || bmtest(g_bm2, i);
  wappend(p1, i, &g_cntn1, g_nl1, NN);
  wappend(p2, i, &g_cntn2, g_nl2, NN);
}

__global__ __launch_bounds__(256) void k_h2(const float* __restrict__ W2, const float* __restrict__ b2){
  __shared__ float sW[64], sb[8];
  int tid = threadIdx.x;
  if (tid < 64) sW[tid] = W2[tid];
  if (tid < 8)  sb[tid] = b2[tid];
  __syncthreads();
  int n = min(g_cntn2, NN);
  int stride = gridDim.x*blockDim.x;
  for (int i = blockIdx.x*blockDim.x + tid; i < n; i += stride){
    int node = g_nl2[i];
    const float* ap = g_agg1 + (size_t)node*8;
    float xv[8], h[8];
    #pragma unroll
    for (int j=0;j<8;j++) xv[j] = fmaxf(ap[j], 0.f);
    #pragma unroll
    for (int j=0;j<8;j++){
      float s2 = 0.f;
      #pragma unroll
      for (int u=0;u<8;u++) s2 += xv[u]*sW[u*8+j];
      h[j] = s2;
    }
    float* hp = g_h + (size_t)node*8;
    #pragma unroll
    for (int j=0;j<8;j++) hp[j] = h[j];
    if (bmtest(g_bm1, node)){
      float r = g_dis[node]; float inv = r*r;
      float* a2 = g_agg2 + (size_t)node*8;
      #pragma unroll
      for (int j=0;j<8;j++) a2[j] = h[j]*inv + sb[j];
    }
  }
}

__global__ void k_agg2(const int* __restrict__ srcp, const int* __restrict__ dstp){
  int n = min(g_cnt1, CAP1);
  int stride = gridDim.x*blockDim.x;
  for (int i = blockIdx.x*blockDim.x + threadIdx.x; i < n; i += stride){
    int e = g_list1[i];
    int s = srcp[e], d = dstp[e];
    float c = g_dis[s]*g_dis[d];
    const float* hp = g_h + (size_t)s*8;
    float4 a = *(const float4*)hp, b = *(const float4*)(hp+4);
    a.x*=c; a.y*=c; a.z*=c; a.w*=c;
    b.x*=c; b.y*=c; b.z*=c; b.w*=c;
    float* ap = g_agg2 + (size_t)d*8;
    atomicAdd((float4*)ap, a);
    atomicAdd((float4*)(ap+4), b);
  }
}

__global__ void k_h3(const float* __restrict__ W3, const float* __restrict__ b3){
  int n = min(g_cntn1, NN);
  int stride = gridDim.x*blockDim.x;
  float w[8];
  #pragma unroll
  for (int j=0;j<8;j++) w[j] = W3[j];
  float bb = b3[0];
  for (int i = blockIdx.x*blockDim.x + threadIdx.x; i < n; i += stride){
    int node = g_nl1[i];
    const float* ap = g_agg2 + (size_t)node*8;
    float s2 = 0.f;
    #pragma unroll
    for (int j=0;j<8;j++) s2 += fmaxf(ap[j], 0.f)*w[j];
    g_h3v[node] = s2;
    if (bmtest(g_bm0, node))
      g_agg3[node] = s2*g_dis[node]*g_dis[node] + bb;
  }
}

__global__ void k_agg3(const int* __restrict__ srcp, const int* __restrict__ dstp){
  int n = min(g_cnt0, CAP0);
  int stride = gridDim.x*blockDim.x;
  for (int i = blockIdx.x*blockDim.x + threadIdx.x; i < n; i += stride){
    int e = g_list0[i];
    int s = srcp[e], d = dstp[e];
    atomicAdd(&g_agg3[d], g_dis[s]*g_dis[d]*g_h3v[s]);
  }
}

// head: feats[17] = [relu(agg1), relu(agg2), relu(agg3)] at targets
__global__ void k_head(const int* __restrict__ tgt,
                       const float* __restrict__ Wl1, const float* __restrict__ bl1,
                       const float* __restrict__ Wl2, const float* __restrict__ bl2,
                       float* __restrict__ out){
  __shared__ float sW1[17*16], sb1[16], sW2[32], sb2[2];
  int tid = threadIdx.x;
  for (int i = tid; i < 17*16; i += 64) sW1[i] = Wl1[i];
  if (tid < 16) sb1[tid] = bl1[tid];
  if (tid < 32) sW2[tid] = Wl2[tid];
  if (tid < 2)  sb2[tid] = bl2[tid];
  __syncthreads();
  if (tid >= NB) return;
  int node = tid*NPG + tgt[tid];
  float f[17];
  const float* a1 = g_agg1 + (size_t)node*8;
  const float* a2 = g_agg2 + (size_t)node*8;
  #pragma unroll
  for (int j=0;j<8;j++) f[j]   = fmaxf(a1[j], 0.f);
  #pragma unroll
  for (int j=0;j<8;j++) f[8+j] = fmaxf(a2[j], 0.f);
  f[16] = fmaxf(g_agg3[node], 0.f);
  float z[16];
  #pragma unroll
  for (int j=0;j<16;j++){
    float s2 = sb1[j];
    #pragma unroll
    for (int u=0;u<17;u++) s2 += f[u]*sW1[u*16+j];
    z[j] = fmaxf(s2, 0.f);
  }
  #pragma unroll
  for (int o=0;o<2;o++){
    float s2 = sb2[o];
    #pragma unroll
    for (int u=0;u<16;u++) s2 += z[u]*sW2[u*2+o];
    out[tid*2+o] = s2;
  }
}

extern "C" void kernel_launch(void* const* d_in, const int* in_sizes, int n_in,
                              void* d_out, int out_size){
  const float* x    = (const float*)d_in[0];
  const int*   ei   = (const int*)  d_in[1];
  const int*   tgt  = (const int*)  d_in[2];
  const float* W1   = (const float*)d_in[3];
  const float* b1   = (const float*)d_in[4];
  const float* W2   = (const float*)d_in[5];
  const float* b2   = (const float*)d_in[6];
  const float* W3   = (const float*)d_in[7];
  const float* b3   = (const float*)d_in[8];
  const float* Wl1  = (const float*)d_in[9];
  const float* bl1  = (const float*)d_in[10];
  const float* Wl2  = (const float*)d_in[11];
  const float* bl2  = (const float*)d_in[12];
  const int* srcp = ei;
  const int* dstp = ei + EE;
  float* out = (float*)d_out;

  k_init<<<NN/256, 256>>>();
  k_mark<<<1, 64>>>(tgt);
  k_deg<<<EE/256, 256>>>(dstp);
  k_srcs<<<64, 256>>>(srcp, 0);
  k_dis<<<NN/256, 256>>>();
  k_h1<<<NN/32, 256>>>(x, W1, b1);
  k_agg1<<<EE/256, 256>>>(srcp, dstp);
  k_srcs<<<64, 256>>>(srcp, 1);
  k_compact<<<NN/256, 256>>>();
  k_h2<<<128, 256>>>(W2, b2);
  k_agg2<<<128, 256>>>(srcp, dstp);
  k_h3<<<128, 256>>>(W3, b3);
  k_agg3<<<64, 256>>>(srcp, dstp);
  k_head<<<1, 64>>>(tgt, Wl1, bl1, Wl2, bl2, out);
}